// round 3
// baseline (speedup 1.0000x reference)
#include <cuda_runtime.h>
#include <cstdint>

#define NN 100000
#define EE 1600000
#define GG 64

// ---------------- scratch (static device memory; no allocs) ----------------
__device__ __align__(16) float g_bufA[NN * 64];
__device__ __align__(16) float g_bufB[NN * 64];
__device__ __align__(16) float g_bufC[NN * 64];
__device__ float    g_norm[EE];
__device__ float    g_deg[NN];
__device__ float    g_dis[NN];
__device__ double   g_sum[64];
__device__ double   g_sumsq[64];
__device__ float    g_scale[64];
__device__ float    g_shift[64];
__device__ unsigned g_pooled[GG * 64];

// ---------------- helpers ----------------
__device__ __forceinline__ void red_add_v4(float* p, float a, float b, float c, float d) {
    asm volatile("red.global.add.v4.f32 [%0], {%1,%2,%3,%4};"
                 :: "l"(p), "f"(a), "f"(b), "f"(c), "f"(d) : "memory");
}

__device__ __forceinline__ unsigned enc_f32(float f) {
    unsigned u = __float_as_uint(f);
    return (u & 0x80000000u) ? ~u : (u | 0x80000000u);
}
__device__ __forceinline__ float dec_f32(unsigned u) {
    return (u & 0x80000000u) ? __uint_as_float(u & 0x7FFFFFFFu) : __uint_as_float(~u);
}

// ---------------- graph normalization ----------------
__global__ void k_deg(const int* __restrict__ ei) {
    int e = blockIdx.x * blockDim.x + threadIdx.x;
    if (e < EE) atomicAdd(&g_deg[ei[e]], 1.0f);
}

__global__ void k_dis() {
    int i = blockIdx.x * blockDim.x + threadIdx.x;
    if (i < NN) {
        float d = g_deg[i];
        g_dis[i] = d > 0.0f ? rsqrtf(d) : 0.0f;
    }
}

__global__ void k_norm(const int* __restrict__ ei) {
    int e = blockIdx.x * blockDim.x + threadIdx.x;
    if (e < EE) g_norm[e] = -g_dis[ei[e]] * g_dis[ei[EE + e]];
}

// ---------------- SpMM: dst[row] += norm[e] * src[col]  (64 feats, 16 lanes/edge) ----------------
__global__ void k_spmm(const float4* __restrict__ src, float* __restrict__ dst,
                       const int* __restrict__ ei) {
    int t = blockIdx.x * blockDim.x + threadIdx.x;
    int e = t >> 4;
    if (e >= EE) return;
    int sub = t & 15;
    float w = g_norm[e];
    int c = ei[EE + e];
    float4 v = src[c * 16 + sub];
    int r = ei[e];
    red_add_v4(dst + (size_t)r * 64 + sub * 4, w * v.x, w * v.y, w * v.z, w * v.w);
}

// ---------------- fused 3-matrix GEMM: out = Z@(W0-W2) + T@W1 + P@(2*W2) + b ----------------
// block = 256 threads, 64 rows/block. thread: 4 rows x 4 cols register tile.
__global__ void k_gemm(const float* Z, const float* T, const float* P,
                       const float* __restrict__ W, const float* __restrict__ bias,
                       float* out) {
    extern __shared__ float sm[];
    float* Ws0 = sm;            // 4096
    float* Ws1 = sm + 4096;
    float* Ws2 = sm + 8192;
    float* Zs  = sm + 12288;    // 64*68 each
    float* Ts  = Zs + 64 * 68;
    float* Ps  = Ts + 64 * 68;

    int tid = threadIdx.x;
    for (int i = tid; i < 4096; i += 256) {
        float w2 = W[8192 + i];
        Ws0[i] = W[i] - w2;
        Ws1[i] = W[4096 + i];
        Ws2[i] = 2.0f * w2;
    }
    int base = blockIdx.x * 64;
    for (int i = tid; i < 1024; i += 256) {
        int r = i >> 4, c = i & 15;
        int row = base + r;
        float4 z4 = make_float4(0.f, 0.f, 0.f, 0.f), t4 = z4, p4 = z4;
        if (row < NN) {
            z4 = ((const float4*)(Z + (size_t)row * 64))[c];
            t4 = ((const float4*)(T + (size_t)row * 64))[c];
            p4 = ((const float4*)(P + (size_t)row * 64))[c];
        }
        *(float4*)(Zs + r * 68 + c * 4) = z4;
        *(float4*)(Ts + r * 68 + c * 4) = t4;
        *(float4*)(Ps + r * 68 + c * 4) = p4;
    }
    __syncthreads();

    int rg = tid >> 4, jc = tid & 15;
    int r0 = rg * 4, j0 = jc * 4;
    float acc[4][4];
    float4 bv = *(const float4*)(bias + j0);
#pragma unroll
    for (int i = 0; i < 4; i++) {
        acc[i][0] = bv.x; acc[i][1] = bv.y; acc[i][2] = bv.z; acc[i][3] = bv.w;
    }

    for (int d4 = 0; d4 < 16; d4++) {
        float za[4][4], ta[4][4], pa[4][4];
#pragma unroll
        for (int i = 0; i < 4; i++) {
            float4 v;
            v = *(const float4*)(Zs + (r0 + i) * 68 + d4 * 4);
            za[i][0] = v.x; za[i][1] = v.y; za[i][2] = v.z; za[i][3] = v.w;
            v = *(const float4*)(Ts + (r0 + i) * 68 + d4 * 4);
            ta[i][0] = v.x; ta[i][1] = v.y; ta[i][2] = v.z; ta[i][3] = v.w;
            v = *(const float4*)(Ps + (r0 + i) * 68 + d4 * 4);
            pa[i][0] = v.x; pa[i][1] = v.y; pa[i][2] = v.z; pa[i][3] = v.w;
        }
#pragma unroll
        for (int dd = 0; dd < 4; dd++) {
            int d = d4 * 4 + dd;
            float4 w0 = *(const float4*)(Ws0 + d * 64 + j0);
            float4 w1 = *(const float4*)(Ws1 + d * 64 + j0);
            float4 w2 = *(const float4*)(Ws2 + d * 64 + j0);
#pragma unroll
            for (int i = 0; i < 4; i++) {
                float z = za[i][dd], tt = ta[i][dd], pp = pa[i][dd];
                acc[i][0] += z * w0.x;  acc[i][1] += z * w0.y;  acc[i][2] += z * w0.z;  acc[i][3] += z * w0.w;
                acc[i][0] += tt * w1.x; acc[i][1] += tt * w1.y; acc[i][2] += tt * w1.z; acc[i][3] += tt * w1.w;
                acc[i][0] += pp * w2.x; acc[i][1] += pp * w2.y; acc[i][2] += pp * w2.z; acc[i][3] += pp * w2.w;
            }
        }
    }
#pragma unroll
    for (int i = 0; i < 4; i++) {
        int row = base + r0 + i;
        if (row < NN)
            *(float4*)(out + (size_t)row * 64 + j0) =
                make_float4(acc[i][0], acc[i][1], acc[i][2], acc[i][3]);
    }
}

// ---------------- shortcut GEMM: out = X @ Wsc + bsc ----------------
__global__ void k_sc(const float* __restrict__ X, const float* __restrict__ W,
                     const float* __restrict__ bias, float* __restrict__ out) {
    __shared__ float Ws[4096];
    __shared__ float Xs[64 * 68];
    int tid = threadIdx.x;
    for (int i = tid; i < 4096; i += 256) Ws[i] = W[i];
    int base = blockIdx.x * 64;
    for (int i = tid; i < 1024; i += 256) {
        int r = i >> 4, c = i & 15;
        int row = base + r;
        float4 v = make_float4(0.f, 0.f, 0.f, 0.f);
        if (row < NN) v = ((const float4*)(X + (size_t)row * 64))[c];
        *(float4*)(Xs + r * 68 + c * 4) = v;
    }
    __syncthreads();
    int rg = tid >> 4, jc = tid & 15;
    int r0 = rg * 4, j0 = jc * 4;
    float acc[4][4];
    float4 bv = *(const float4*)(bias + j0);
#pragma unroll
    for (int i = 0; i < 4; i++) {
        acc[i][0] = bv.x; acc[i][1] = bv.y; acc[i][2] = bv.z; acc[i][3] = bv.w;
    }
    for (int d4 = 0; d4 < 16; d4++) {
        float xa[4][4];
#pragma unroll
        for (int i = 0; i < 4; i++) {
            float4 v = *(const float4*)(Xs + (r0 + i) * 68 + d4 * 4);
            xa[i][0] = v.x; xa[i][1] = v.y; xa[i][2] = v.z; xa[i][3] = v.w;
        }
#pragma unroll
        for (int dd = 0; dd < 4; dd++) {
            float4 w = *(const float4*)(Ws + (d4 * 4 + dd) * 64 + j0);
#pragma unroll
            for (int i = 0; i < 4; i++) {
                float xx = xa[i][dd];
                acc[i][0] += xx * w.x; acc[i][1] += xx * w.y;
                acc[i][2] += xx * w.z; acc[i][3] += xx * w.w;
            }
        }
    }
#pragma unroll
    for (int i = 0; i < 4; i++) {
        int row = base + r0 + i;
        if (row < NN)
            *(float4*)(out + (size_t)row * 64 + j0) =
                make_float4(acc[i][0], acc[i][1], acc[i][2], acc[i][3]);
    }
}

// ---------------- BN stats: per-feature sum / sumsq ----------------
__global__ void k_stats(const float* __restrict__ H) {
    __shared__ float sh[256], sh2[256];
    int j = threadIdx.x & 63, rl = threadIdx.x >> 6;
    float s = 0.f, q = 0.f;
    for (int r = blockIdx.x * 4 + rl; r < NN; r += gridDim.x * 4) {
        float v = H[(size_t)r * 64 + j];
        s += v;
        q += v * v;
    }
    sh[threadIdx.x] = s;
    sh2[threadIdx.x] = q;
    __syncthreads();
    if (rl == 0) {
        s = sh[j] + sh[64 + j] + sh[128 + j] + sh[192 + j];
        q = sh2[j] + sh2[64 + j] + sh2[128 + j] + sh2[192 + j];
        atomicAdd(&g_sum[j], (double)s);
        atomicAdd(&g_sumsq[j], (double)q);
    }
}

__global__ void k_finalize(const float* __restrict__ g, const float* __restrict__ be) {
    int j = threadIdx.x;
    double mu = g_sum[j] / (double)NN;
    double var = g_sumsq[j] / (double)NN - mu * mu;
    float sc = g[j] * (float)(1.0 / sqrt(var + 1e-5));
    g_scale[j] = sc;
    g_shift[j] = be[j] - (float)mu * sc;
}

// ---------------- BN apply + leaky ReLU (in place) ----------------
__global__ void k_apply(float* __restrict__ H) {
    int i = blockIdx.x * blockDim.x + threadIdx.x;
    if (i < NN * 64) {
        int j = i & 63;
        float v = H[i] * g_scale[j] + g_shift[j];
        H[i] = v > 0.f ? v : 0.01f * v;
    }
}

// ---------------- layer 3: BN apply + lrelu + shortcut + segment-max pool ----------------
__global__ void k_apply3(const float* __restrict__ pre, const float* __restrict__ sc,
                         const int* __restrict__ batch) {
    int i = blockIdx.x * blockDim.x + threadIdx.x;
    if (i >= NN * 64) return;
    int j = i & 63, row = i >> 6;
    float v = pre[i] * g_scale[j] + g_shift[j];
    v = v > 0.f ? v : 0.01f * v;
    v += sc[i];
    atomicMax(&g_pooled[batch[row] * 64 + j], enc_f32(v));
}

// ---------------- final: pooled @ w_lin + b_lin ----------------
__global__ void k_final(const float* __restrict__ wlin, const float* __restrict__ blin,
                        float* __restrict__ out) {
    int g = blockIdx.x, j = threadIdx.x;
    float v = dec_f32(g_pooled[g * 64 + j]) * wlin[j];
#pragma unroll
    for (int o = 16; o > 0; o >>= 1) v += __shfl_down_sync(0xffffffffu, v, o);
    __shared__ float s2[2];
    if ((j & 31) == 0) s2[j >> 5] = v;
    __syncthreads();
    if (j == 0) out[g] = s2[0] + s2[1] + blin[0];
}

// ---------------- launcher ----------------
extern "C" void kernel_launch(void* const* d_in, const int* in_sizes, int n_in,
                              void* d_out, int out_size) {
    const float* x     = (const float*)d_in[0];
    const int*   ei    = (const int*)d_in[1];      // int32 (JAX default x64-disabled)
    const int*   batch = (const int*)d_in[2];
    const float* W[3]  = {(const float*)d_in[3], (const float*)d_in[5], (const float*)d_in[7]};
    const float* B[3]  = {(const float*)d_in[4], (const float*)d_in[6], (const float*)d_in[8]};
    const float* Ga[3] = {(const float*)d_in[9], (const float*)d_in[11], (const float*)d_in[13]};
    const float* Be[3] = {(const float*)d_in[10], (const float*)d_in[12], (const float*)d_in[14]};
    const float* wsc  = (const float*)d_in[15];
    const float* bsc  = (const float*)d_in[16];
    const float* wlin = (const float*)d_in[17];
    const float* blin = (const float*)d_in[18];
    float* out = (float*)d_out;

    const int GEMM_SMEM = (12288 + 3 * 64 * 68) * 4;  // 101376 B
    cudaFuncSetAttribute(k_gemm, cudaFuncAttributeMaxDynamicSharedMemorySize, GEMM_SMEM);

    void *pA, *pB, *pC, *pdeg, *psum, *psumsq, *ppool;
    cudaGetSymbolAddress(&pA, g_bufA);
    cudaGetSymbolAddress(&pB, g_bufB);
    cudaGetSymbolAddress(&pC, g_bufC);
    cudaGetSymbolAddress(&pdeg, g_deg);
    cudaGetSymbolAddress(&psum, g_sum);
    cudaGetSymbolAddress(&psumsq, g_sumsq);
    cudaGetSymbolAddress(&ppool, g_pooled);

    float* bufA = (float*)pA;
    float* bufB = (float*)pB;
    float* bufC = (float*)pC;

    const int EB = (EE + 255) / 256;           // edge-grid
    const int SB = (EE * 16 + 255) / 256;      // spmm grid
    const int NB = (NN + 255) / 256;
    const int FB = (NN * 64 + 255) / 256;      // feature-elementwise grid
    const int GB = (NN + 63) / 64;             // gemm grid

    cudaMemsetAsync(pdeg, 0, NN * sizeof(float));
    k_deg<<<EB, 256>>>(ei);
    k_dis<<<NB, 256>>>();
    k_norm<<<EB, 256>>>(ei);

    const float* Zcur = x;
    for (int l = 0; l < 3; l++) {
        cudaMemsetAsync(pA, 0, (size_t)NN * 64 * sizeof(float));
        k_spmm<<<SB, 256>>>((const float4*)Zcur, bufA, ei);          // T1 = prop(Z)
        cudaMemsetAsync(pB, 0, (size_t)NN * 64 * sizeof(float));
        k_spmm<<<SB, 256>>>((const float4*)bufA, bufB, ei);          // P = prop(T1)
        k_gemm<<<GB, 256, GEMM_SMEM>>>(Zcur, bufA, bufB, W[l], B[l], bufC);
        cudaMemsetAsync(psum, 0, 64 * sizeof(double));
        cudaMemsetAsync(psumsq, 0, 64 * sizeof(double));
        k_stats<<<256, 256>>>(bufC);
        k_finalize<<<1, 64>>>(Ga[l], Be[l]);
        if (l < 2) k_apply<<<FB, 256>>>(bufC);
        Zcur = bufC;
    }

    k_sc<<<GB, 256>>>(x, wsc, bsc, bufA);                            // shortcut into bufA
    cudaMemsetAsync(ppool, 0, GG * 64 * sizeof(unsigned));
    k_apply3<<<FB, 256>>>(bufC, bufA, batch);
    k_final<<<GG, 64>>>(wlin, blin, out);
}

// round 5
// speedup vs baseline: 1.0797x; 1.0797x over previous
#include <cuda_runtime.h>
#include <cstdint>

#define NN 100000
#define EE 1600000
#define GG 64
#define SCAN_B 391   // ceil(NN/256)

// ---------------- scratch (static device memory; no allocs) ----------------
__device__ __align__(16) float g_bufA[NN * 64];
__device__ __align__(16) float g_bufB[NN * 64];
__device__ __align__(16) float g_bufC[NN * 64];
__device__ int      g_cnt[NN];
__device__ int      g_scan[NN];
__device__ int      g_bsum[SCAN_B];
__device__ int      g_boff[SCAN_B];
__device__ int      g_rowptr[NN + 1];
__device__ int      g_cursor[NN];
__device__ __align__(8) int2 g_csr[EE];   // (col, w-bits)
__device__ float    g_dis[NN];
__device__ double   g_sum[64];
__device__ double   g_sumsq[64];
__device__ float    g_scale[64];
__device__ float    g_shift[64];
__device__ unsigned g_pooled[GG * 64];

// ---------------- helpers ----------------
__device__ __forceinline__ unsigned enc_f32(float f) {
    unsigned u = __float_as_uint(f);
    return (u & 0x80000000u) ? ~u : (u | 0x80000000u);
}
__device__ __forceinline__ float dec_f32(unsigned u) {
    return (u & 0x80000000u) ? __uint_as_float(u & 0x7FFFFFFFu) : __uint_as_float(~u);
}

// ---------------- degree histogram (int) ----------------
__global__ void k_deg(const int* __restrict__ ei) {
    int e = blockIdx.x * blockDim.x + threadIdx.x;
    if (e < EE) atomicAdd(&g_cnt[ei[e]], 1);
}

__global__ void k_dis() {
    int i = blockIdx.x * blockDim.x + threadIdx.x;
    if (i < NN) {
        int d = g_cnt[i];
        g_dis[i] = d > 0 ? rsqrtf((float)d) : 0.0f;
    }
}

// ---------------- 3-step exclusive scan of degrees -> rowptr ----------------
__global__ void k_scan1() {
    __shared__ int sh[256];
    int t = threadIdx.x, i = blockIdx.x * 256 + t;
    int v = (i < NN) ? g_cnt[i] : 0;
    sh[t] = v;
    __syncthreads();
    for (int o = 1; o < 256; o <<= 1) {
        int x = (t >= o) ? sh[t - o] : 0;
        __syncthreads();
        sh[t] += x;
        __syncthreads();
    }
    if (i < NN) g_scan[i] = sh[t];
    if (t == 255) g_bsum[blockIdx.x] = sh[255];
}

__global__ void k_scan2() {
    __shared__ int sh[512];
    int t = threadIdx.x;
    int v = (t < SCAN_B) ? g_bsum[t] : 0;
    sh[t] = v;
    __syncthreads();
    for (int o = 1; o < 512; o <<= 1) {
        int x = (t >= o) ? sh[t - o] : 0;
        __syncthreads();
        sh[t] += x;
        __syncthreads();
    }
    if (t < SCAN_B) g_boff[t] = sh[t] - v;  // exclusive
}

__global__ void k_scan3() {
    int i = blockIdx.x * blockDim.x + threadIdx.x;
    if (i < NN) {
        int rp = g_scan[i] - g_cnt[i] + g_boff[i >> 8];
        g_rowptr[i] = rp;
        g_cursor[i] = rp;
    }
    if (i == 0) g_rowptr[NN] = EE;
}

// ---------------- CSR fill (norm folded in) ----------------
__global__ void k_fill(const int* __restrict__ ei) {
    int e = blockIdx.x * blockDim.x + threadIdx.x;
    if (e >= EE) return;
    int r = ei[e], c = ei[EE + e];
    float w = -g_dis[r] * g_dis[c];
    int pos = atomicAdd(&g_cursor[r], 1);
    g_csr[pos] = make_int2(c, __float_as_int(w));
}

// ---------------- CSR SpMM: one warp per row, float2 per lane ----------------
__global__ __launch_bounds__(256) void k_spmm_csr(const float2* __restrict__ src,
                                                  float2* __restrict__ dst) {
    int row = blockIdx.x * 8 + (threadIdx.x >> 5);
    if (row >= NN) return;
    int lane = threadIdx.x & 31;
    int p = g_rowptr[row], pe = g_rowptr[row + 1];
    float2 acc = make_float2(0.f, 0.f);
    for (; p + 2 <= pe; p += 2) {
        int2 a = g_csr[p];
        int2 b = g_csr[p + 1];
        float2 v0 = src[(size_t)a.x * 32 + lane];
        float2 v1 = src[(size_t)b.x * 32 + lane];
        float w0 = __int_as_float(a.y), w1 = __int_as_float(b.y);
        acc.x += w0 * v0.x; acc.y += w0 * v0.y;
        acc.x += w1 * v1.x; acc.y += w1 * v1.y;
    }
    if (p < pe) {
        int2 a = g_csr[p];
        float2 v0 = src[(size_t)a.x * 32 + lane];
        float w0 = __int_as_float(a.y);
        acc.x += w0 * v0.x; acc.y += w0 * v0.y;
    }
    dst[(size_t)row * 32 + lane] = acc;
}

// ---------------- fused 3-matrix GEMM + BN-stats epilogue ----------------
// out = Z@(W0-W2) + T@W1 + P@(2*W2) + b ; also accumulates sum/sumsq per feature.
__global__ __launch_bounds__(256) void k_gemm(const float* Z, const float* T, const float* P,
                       const float* __restrict__ W, const float* __restrict__ bias,
                       float* out) {
    extern __shared__ float sm[];
    float* Ws0 = sm;            // 4096
    float* Ws1 = sm + 4096;
    float* Ws2 = sm + 8192;
    float* Zs  = sm + 12288;    // 64*68 each
    float* Ts  = Zs + 64 * 68;
    float* Ps  = Ts + 64 * 68;

    int tid = threadIdx.x;
    for (int i = tid; i < 4096; i += 256) {
        float w2 = W[8192 + i];
        Ws0[i] = W[i] - w2;
        Ws1[i] = W[4096 + i];
        Ws2[i] = 2.0f * w2;
    }
    int base = blockIdx.x * 64;
    for (int i = tid; i < 1024; i += 256) {
        int r = i >> 4, c = i & 15;
        int row = base + r;
        float4 z4 = make_float4(0.f, 0.f, 0.f, 0.f), t4 = z4, p4 = z4;
        if (row < NN) {
            z4 = ((const float4*)(Z + (size_t)row * 64))[c];
            t4 = ((const float4*)(T + (size_t)row * 64))[c];
            p4 = ((const float4*)(P + (size_t)row * 64))[c];
        }
        *(float4*)(Zs + r * 68 + c * 4) = z4;
        *(float4*)(Ts + r * 68 + c * 4) = t4;
        *(float4*)(Ps + r * 68 + c * 4) = p4;
    }
    __syncthreads();

    int rg = tid >> 4, jc = tid & 15;
    int r0 = rg * 4, j0 = jc * 4;
    float acc[4][4];
    float4 bv = *(const float4*)(bias + j0);
#pragma unroll
    for (int i = 0; i < 4; i++) {
        acc[i][0] = bv.x; acc[i][1] = bv.y; acc[i][2] = bv.z; acc[i][3] = bv.w;
    }

    for (int d4 = 0; d4 < 16; d4++) {
        float za[4][4], ta[4][4], pa[4][4];
#pragma unroll
        for (int i = 0; i < 4; i++) {
            float4 v;
            v = *(const float4*)(Zs + (r0 + i) * 68 + d4 * 4);
            za[i][0] = v.x; za[i][1] = v.y; za[i][2] = v.z; za[i][3] = v.w;
            v = *(const float4*)(Ts + (r0 + i) * 68 + d4 * 4);
            ta[i][0] = v.x; ta[i][1] = v.y; ta[i][2] = v.z; ta[i][3] = v.w;
            v = *(const float4*)(Ps + (r0 + i) * 68 + d4 * 4);
            pa[i][0] = v.x; pa[i][1] = v.y; pa[i][2] = v.z; pa[i][3] = v.w;
        }
#pragma unroll
        for (int dd = 0; dd < 4; dd++) {
            int d = d4 * 4 + dd;
            float4 w0 = *(const float4*)(Ws0 + d * 64 + j0);
            float4 w1 = *(const float4*)(Ws1 + d * 64 + j0);
            float4 w2 = *(const float4*)(Ws2 + d * 64 + j0);
#pragma unroll
            for (int i = 0; i < 4; i++) {
                float z = za[i][dd], tt = ta[i][dd], pp = pa[i][dd];
                acc[i][0] += z * w0.x;  acc[i][1] += z * w0.y;  acc[i][2] += z * w0.z;  acc[i][3] += z * w0.w;
                acc[i][0] += tt * w1.x; acc[i][1] += tt * w1.y; acc[i][2] += tt * w1.z; acc[i][3] += tt * w1.w;
                acc[i][0] += pp * w2.x; acc[i][1] += pp * w2.y; acc[i][2] += pp * w2.z; acc[i][3] += pp * w2.w;
            }
        }
    }
#pragma unroll
    for (int i = 0; i < 4; i++) {
        int row = base + r0 + i;
        if (row < NN)
            *(float4*)(out + (size_t)row * 64 + j0) =
                make_float4(acc[i][0], acc[i][1], acc[i][2], acc[i][3]);
    }

    // ---- BN stats epilogue: column sums / sumsq over valid rows ----
    float ps[4] = {0.f, 0.f, 0.f, 0.f}, pq[4] = {0.f, 0.f, 0.f, 0.f};
#pragma unroll
    for (int i = 0; i < 4; i++) {
        if (base + r0 + i < NN) {
#pragma unroll
            for (int c = 0; c < 4; c++) {
                float v = acc[i][c];
                ps[c] += v;
                pq[c] += v * v;
            }
        }
    }
    __syncthreads();                 // done reading Zs/Ts/Ps — safe to reuse
    float* s1 = Zs;                  // [16][64]
    float* s2 = Zs + 1024;           // [16][64]
#pragma unroll
    for (int c = 0; c < 4; c++) {
        s1[rg * 64 + j0 + c] = ps[c];
        s2[rg * 64 + j0 + c] = pq[c];
    }
    __syncthreads();
    if (tid < 64) {
        float s = 0.f, q = 0.f;
#pragma unroll
        for (int r = 0; r < 16; r++) {
            s += s1[r * 64 + tid];
            q += s2[r * 64 + tid];
        }
        atomicAdd(&g_sum[tid], (double)s);
        atomicAdd(&g_sumsq[tid], (double)q);
    }
}

// ---------------- shortcut GEMM: out = X @ Wsc + bsc ----------------
__global__ __launch_bounds__(256) void k_sc(const float* __restrict__ X, const float* __restrict__ W,
                     const float* __restrict__ bias, float* __restrict__ out) {
    __shared__ float Ws[4096];
    __shared__ float Xs[64 * 68];
    int tid = threadIdx.x;
    for (int i = tid; i < 4096; i += 256) Ws[i] = W[i];
    int base = blockIdx.x * 64;
    for (int i = tid; i < 1024; i += 256) {
        int r = i >> 4, c = i & 15;
        int row = base + r;
        float4 v = make_float4(0.f, 0.f, 0.f, 0.f);
        if (row < NN) v = ((const float4*)(X + (size_t)row * 64))[c];
        *(float4*)(Xs + r * 68 + c * 4) = v;
    }
    __syncthreads();
    int rg = tid >> 4, jc = tid & 15;
    int r0 = rg * 4, j0 = jc * 4;
    float acc[4][4];
    float4 bv = *(const float4*)(bias + j0);
#pragma unroll
    for (int i = 0; i < 4; i++) {
        acc[i][0] = bv.x; acc[i][1] = bv.y; acc[i][2] = bv.z; acc[i][3] = bv.w;
    }
    for (int d4 = 0; d4 < 16; d4++) {
        float xa[4][4];
#pragma unroll
        for (int i = 0; i < 4; i++) {
            float4 v = *(const float4*)(Xs + (r0 + i) * 68 + d4 * 4);
            xa[i][0] = v.x; xa[i][1] = v.y; xa[i][2] = v.z; xa[i][3] = v.w;
        }
#pragma unroll
        for (int dd = 0; dd < 4; dd++) {
            float4 w = *(const float4*)(Ws + (d4 * 4 + dd) * 64 + j0);
#pragma unroll
            for (int i = 0; i < 4; i++) {
                float xx = xa[i][dd];
                acc[i][0] += xx * w.x; acc[i][1] += xx * w.y;
                acc[i][2] += xx * w.z; acc[i][3] += xx * w.w;
            }
        }
    }
#pragma unroll
    for (int i = 0; i < 4; i++) {
        int row = base + r0 + i;
        if (row < NN)
            *(float4*)(out + (size_t)row * 64 + j0) =
                make_float4(acc[i][0], acc[i][1], acc[i][2], acc[i][3]);
    }
}

__global__ void k_finalize(const float* __restrict__ g, const float* __restrict__ be) {
    int j = threadIdx.x;
    double mu = g_sum[j] / (double)NN;
    double var = g_sumsq[j] / (double)NN - mu * mu;
    float sc = g[j] * (float)(1.0 / sqrt(var + 1e-5));
    g_scale[j] = sc;
    g_shift[j] = be[j] - (float)mu * sc;
}

// ---------------- BN apply + leaky ReLU (in place) ----------------
__global__ void k_apply(float* __restrict__ H) {
    int i = blockIdx.x * blockDim.x + threadIdx.x;
    if (i < NN * 64) {
        int j = i & 63;
        float v = H[i] * g_scale[j] + g_shift[j];
        H[i] = v > 0.f ? v : 0.01f * v;
    }
}

// ---------------- layer 3: BN apply + lrelu + shortcut + segment-max pool ----------------
__global__ void k_apply3(const float* __restrict__ pre, const float* __restrict__ sc,
                         const int* __restrict__ batch) {
    int i = blockIdx.x * blockDim.x + threadIdx.x;
    if (i >= NN * 64) return;
    int j = i & 63, row = i >> 6;
    float v = pre[i] * g_scale[j] + g_shift[j];
    v = v > 0.f ? v : 0.01f * v;
    v += sc[i];
    atomicMax(&g_pooled[batch[row] * 64 + j], enc_f32(v));
}

// ---------------- final: pooled @ w_lin + b_lin ----------------
__global__ void k_final(const float* __restrict__ wlin, const float* __restrict__ blin,
                        float* __restrict__ out) {
    int g = blockIdx.x, j = threadIdx.x;
    float v = dec_f32(g_pooled[g * 64 + j]) * wlin[j];
#pragma unroll
    for (int o = 16; o > 0; o >>= 1) v += __shfl_down_sync(0xffffffffu, v, o);
    __shared__ float s2[2];
    if ((j & 31) == 0) s2[j >> 5] = v;
    __syncthreads();
    if (j == 0) out[g] = s2[0] + s2[1] + blin[0];
}

// ---------------- launcher ----------------
extern "C" void kernel_launch(void* const* d_in, const int* in_sizes, int n_in,
                              void* d_out, int out_size) {
    const float* x     = (const float*)d_in[0];
    const int*   ei    = (const int*)d_in[1];
    const int*   batch = (const int*)d_in[2];
    const float* W[3]  = {(const float*)d_in[3], (const float*)d_in[5], (const float*)d_in[7]};
    const float* B[3]  = {(const float*)d_in[4], (const float*)d_in[6], (const float*)d_in[8]};
    const float* Ga[3] = {(const float*)d_in[9], (const float*)d_in[11], (const float*)d_in[13]};
    const float* Be[3] = {(const float*)d_in[10], (const float*)d_in[12], (const float*)d_in[14]};
    const float* wsc  = (const float*)d_in[15];
    const float* bsc  = (const float*)d_in[16];
    const float* wlin = (const float*)d_in[17];
    const float* blin = (const float*)d_in[18];
    float* out = (float*)d_out;

    const int GEMM_SMEM = (12288 + 3 * 64 * 68) * 4;  // 101376 B
    cudaFuncSetAttribute(k_gemm, cudaFuncAttributeMaxDynamicSharedMemorySize, GEMM_SMEM);

    void *pA, *pB, *pC, *pcnt, *psum, *psumsq, *ppool;
    cudaGetSymbolAddress(&pA, g_bufA);
    cudaGetSymbolAddress(&pB, g_bufB);
    cudaGetSymbolAddress(&pC, g_bufC);
    cudaGetSymbolAddress(&pcnt, g_cnt);
    cudaGetSymbolAddress(&psum, g_sum);
    cudaGetSymbolAddress(&psumsq, g_sumsq);
    cudaGetSymbolAddress(&ppool, g_pooled);

    float* bufA = (float*)pA;
    float* bufB = (float*)pB;
    float* bufC = (float*)pC;

    const int EB = (EE + 255) / 256;
    const int NB = (NN + 255) / 256;
    const int FB = (NN * 64 + 255) / 256;
    const int GB = (NN + 63) / 64;
    const int SPB = (NN + 7) / 8;             // spmm: 8 rows (warps) per block

    // ---- CSR build ----
    cudaMemsetAsync(pcnt, 0, NN * sizeof(int));
    k_deg<<<EB, 256>>>(ei);
    k_dis<<<NB, 256>>>();
    k_scan1<<<SCAN_B, 256>>>();
    k_scan2<<<1, 512>>>();
    k_scan3<<<NB, 256>>>();
    k_fill<<<EB, 256>>>(ei);

    // ---- layers ----
    const float* Zcur = x;
    for (int l = 0; l < 3; l++) {
        k_spmm_csr<<<SPB, 256>>>((const float2*)Zcur, (float2*)bufA);   // T1
        k_spmm_csr<<<SPB, 256>>>((const float2*)bufA, (float2*)bufB);   // P
        cudaMemsetAsync(psum, 0, 64 * sizeof(double));
        cudaMemsetAsync(psumsq, 0, 64 * sizeof(double));
        k_gemm<<<GB, 256, GEMM_SMEM>>>(Zcur, bufA, bufB, W[l], B[l], bufC);
        k_finalize<<<1, 64>>>(Ga[l], Be[l]);
        if (l < 2) k_apply<<<FB, 256>>>(bufC);
        Zcur = bufC;
    }

    k_sc<<<GB, 256>>>(x, wsc, bsc, bufA);
    cudaMemsetAsync(ppool, 0, GG * 64 * sizeof(unsigned));
    k_apply3<<<FB, 256>>>(bufC, bufA, batch);
    k_final<<<GG, 64>>>(wlin, blin, out);
}

// round 6
// speedup vs baseline: 1.2650x; 1.1717x over previous
#include <cuda_runtime.h>
#include <cstdint>

#define NN 100000
#define EE 1600000
#define GG 64
#define SCAN_B 391   // ceil(NN/256)

typedef unsigned long long u64;

// ---------------- scratch (static device memory; no allocs) ----------------
__device__ __align__(16) float g_bufA[NN * 64];
__device__ __align__(16) float g_bufB[NN * 64];
__device__ __align__(16) float g_bufC[NN * 64];
__device__ int      g_cnt[NN];
__device__ int      g_scan[NN];
__device__ int      g_bsum[SCAN_B];
__device__ int      g_boff[SCAN_B];
__device__ int      g_rowptr[NN + 1];
__device__ int      g_cursor[NN];
__device__ __align__(8) int2 g_csr[EE];   // (col, w-bits)
__device__ float    g_dis[NN];
__device__ double   g_sum[64];
__device__ double   g_sumsq[64];
__device__ float    g_scale[64];
__device__ float    g_shift[64];
__device__ unsigned g_pooled[GG * 64];

// ---------------- helpers ----------------
__device__ __forceinline__ unsigned enc_f32(float f) {
    unsigned u = __float_as_uint(f);
    return (u & 0x80000000u) ? ~u : (u | 0x80000000u);
}
__device__ __forceinline__ float dec_f32(unsigned u) {
    return (u & 0x80000000u) ? __uint_as_float(u & 0x7FFFFFFFu) : __uint_as_float(~u);
}
__device__ __forceinline__ u64 splat2(float f) {
    u64 r;
    unsigned u = __float_as_uint(f);
    asm("mov.b64 %0, {%1,%2};" : "=l"(r) : "r"(u), "r"(u));
    return r;
}
#define FMA2(acc, a, w) asm("fma.rn.f32x2 %0, %1, %2, %0;" : "+l"(acc) : "l"(a), "l"(w))
__device__ __forceinline__ void unpack2(u64 v, float& lo, float& hi) {
    unsigned a, b;
    asm("mov.b64 {%0,%1}, %2;" : "=r"(a), "=r"(b) : "l"(v));
    lo = __uint_as_float(a);
    hi = __uint_as_float(b);
}

// ---------------- degree histogram (int) ----------------
__global__ void k_deg(const int* __restrict__ ei) {
    int e = blockIdx.x * blockDim.x + threadIdx.x;
    if (e < EE) atomicAdd(&g_cnt[ei[e]], 1);
}

// ---------------- scan phase 1 (+ fused dis) ----------------
__global__ void k_scan1() {
    __shared__ int sh[256];
    int t = threadIdx.x, i = blockIdx.x * 256 + t;
    int v = (i < NN) ? g_cnt[i] : 0;
    if (i < NN) g_dis[i] = v > 0 ? rsqrtf((float)v) : 0.0f;
    sh[t] = v;
    __syncthreads();
    for (int o = 1; o < 256; o <<= 1) {
        int x = (t >= o) ? sh[t - o] : 0;
        __syncthreads();
        sh[t] += x;
        __syncthreads();
    }
    if (i < NN) g_scan[i] = sh[t];
    if (t == 255) g_bsum[blockIdx.x] = sh[255];
}

__global__ void k_scan2() {
    __shared__ int sh[512];
    int t = threadIdx.x;
    int v = (t < SCAN_B) ? g_bsum[t] : 0;
    sh[t] = v;
    __syncthreads();
    for (int o = 1; o < 512; o <<= 1) {
        int x = (t >= o) ? sh[t - o] : 0;
        __syncthreads();
        sh[t] += x;
        __syncthreads();
    }
    if (t < SCAN_B) g_boff[t] = sh[t] - v;  // exclusive
}

__global__ void k_scan3() {
    int i = blockIdx.x * blockDim.x + threadIdx.x;
    if (i < NN) {
        int rp = g_scan[i] - g_cnt[i] + g_boff[i >> 8];
        g_rowptr[i] = rp;
        g_cursor[i] = rp;
    }
    if (i == 0) g_rowptr[NN] = EE;
}

// ---------------- CSR fill (norm folded in) ----------------
__global__ void k_fill(const int* __restrict__ ei) {
    int e = blockIdx.x * blockDim.x + threadIdx.x;
    if (e >= EE) return;
    int r = ei[e], c = ei[EE + e];
    float w = -g_dis[r] * g_dis[c];
    int pos = atomicAdd(&g_cursor[r], 1);
    g_csr[pos] = make_int2(c, __float_as_int(w));
}

// ---------------- CSR SpMM: one warp per row, float2 per lane, unroll 4 ----------------
__global__ __launch_bounds__(256) void k_spmm_csr(const float2* __restrict__ src,
                                                  float2* __restrict__ dst) {
    int row = blockIdx.x * 8 + (threadIdx.x >> 5);
    if (row >= NN) return;
    int lane = threadIdx.x & 31;
    int p = g_rowptr[row], pe = g_rowptr[row + 1];
    float2 acc = make_float2(0.f, 0.f);
    for (; p + 4 <= pe; p += 4) {
        int2 e0 = g_csr[p];
        int2 e1 = g_csr[p + 1];
        int2 e2 = g_csr[p + 2];
        int2 e3 = g_csr[p + 3];
        float2 v0 = src[(size_t)e0.x * 32 + lane];
        float2 v1 = src[(size_t)e1.x * 32 + lane];
        float2 v2 = src[(size_t)e2.x * 32 + lane];
        float2 v3 = src[(size_t)e3.x * 32 + lane];
        float w0 = __int_as_float(e0.y), w1 = __int_as_float(e1.y);
        float w2 = __int_as_float(e2.y), w3 = __int_as_float(e3.y);
        acc.x += w0 * v0.x; acc.y += w0 * v0.y;
        acc.x += w1 * v1.x; acc.y += w1 * v1.y;
        acc.x += w2 * v2.x; acc.y += w2 * v2.y;
        acc.x += w3 * v3.x; acc.y += w3 * v3.y;
    }
    for (; p < pe; p++) {
        int2 a = g_csr[p];
        float2 v = src[(size_t)a.x * 32 + lane];
        float w = __int_as_float(a.y);
        acc.x += w * v.x; acc.y += w * v.y;
    }
    dst[(size_t)row * 32 + lane] = acc;
}

// ---------------- fused 3-matrix GEMM (f32x2) + BN-stats epilogue ----------------
// out = Z@(W0-W2) + T@W1 + P@(2*W2) + b, viewed as [Z|T|P](128rows x 192) @ W'(192 x 64).
// smem: Wd[192][64] pre-splatted float2 pairs (96KB) + At[192][128] transposed A (96KB).
// 512 threads; warp w owns cols 4w..4w+3; lane owns row-pairs {2l,2l+1},{64+2l,64+2l+1}.
__global__ __launch_bounds__(512, 1) void k_gemm3(const float* __restrict__ Z,
                                                  const float* __restrict__ T,
                                                  const float* __restrict__ P,
                                                  const float* __restrict__ W,
                                                  const float* __restrict__ bias,
                                                  float* __restrict__ out) {
    extern __shared__ float sm[];
    float* Wd = sm;                 // 192*128 floats (splatted pairs)
    float* At = sm + 192 * 128;     // 192*128 floats

    int tid = threadIdx.x;
    int base = blockIdx.x * 128;

    // -- weights: fold Chebyshev recurrence, splat each value --
    for (int i = tid; i < 192 * 64; i += 512) {
        int kk = i >> 6, c = i & 63;
        int m = kk >> 6, kr = kk & 63;
        float w = W[m * 4096 + kr * 64 + c];
        if (m == 0) w -= W[8192 + kr * 64 + c];
        else if (m == 2) w *= 2.0f;
        float2* d = (float2*)(Wd + (size_t)kk * 128 + c * 2);
        *d = make_float2(w, w);
    }
    // -- A tiles transposed --
    const float4* srcs[3] = {(const float4*)Z, (const float4*)T, (const float4*)P};
#pragma unroll
    for (int m = 0; m < 3; m++) {
        const float4* s = srcs[m];
        for (int i = tid; i < 128 * 16; i += 512) {
            int row = i & 127, c4 = i >> 7;
            float4 v = make_float4(0.f, 0.f, 0.f, 0.f);
            if (base + row < NN) v = s[(size_t)(base + row) * 16 + c4];
            float* d = At + (size_t)(m * 64 + c4 * 4) * 128 + row;
            d[0] = v.x; d[128] = v.y; d[256] = v.z; d[384] = v.w;
        }
    }
    __syncthreads();

    int warp = tid >> 5, lane = tid & 31;
    int j0 = warp * 4;

    u64 acc[2][4];
#pragma unroll
    for (int c = 0; c < 4; c++) {
        u64 b = splat2(bias[j0 + c]);
        acc[0][c] = b;
        acc[1][c] = b;
    }

    const char* wb = (const char*)(Wd + j0 * 2);     // + kk*512B
    const char* ab = (const char*)(At + 2 * lane);   // + kk*512B

#pragma unroll 4
    for (int kk = 0; kk < 192; kk++) {
        ulonglong2 w01 = *(const ulonglong2*)(wb + (size_t)kk * 512);
        ulonglong2 w23 = *(const ulonglong2*)(wb + (size_t)kk * 512 + 16);
        u64 a0 = *(const u64*)(ab + (size_t)kk * 512);
        u64 a1 = *(const u64*)(ab + (size_t)kk * 512 + 256);
        FMA2(acc[0][0], a0, w01.x); FMA2(acc[0][1], a0, w01.y);
        FMA2(acc[0][2], a0, w23.x); FMA2(acc[0][3], a0, w23.y);
        FMA2(acc[1][0], a1, w01.x); FMA2(acc[1][1], a1, w01.y);
        FMA2(acc[1][2], a1, w23.x); FMA2(acc[1][3], a1, w23.y);
    }

    // -- store + BN partials --
    float s[4] = {0.f, 0.f, 0.f, 0.f}, q[4] = {0.f, 0.f, 0.f, 0.f};
#pragma unroll
    for (int rp = 0; rp < 2; rp++) {
        int re = base + rp * 64 + 2 * lane;
        float lo[4], hi[4];
#pragma unroll
        for (int c = 0; c < 4; c++) unpack2(acc[rp][c], lo[c], hi[c]);
        if (re < NN) {
            *(float4*)(out + (size_t)re * 64 + j0) = make_float4(lo[0], lo[1], lo[2], lo[3]);
#pragma unroll
            for (int c = 0; c < 4; c++) { s[c] += lo[c]; q[c] += lo[c] * lo[c]; }
        }
        if (re + 1 < NN) {
            *(float4*)(out + (size_t)(re + 1) * 64 + j0) = make_float4(hi[0], hi[1], hi[2], hi[3]);
#pragma unroll
            for (int c = 0; c < 4; c++) { s[c] += hi[c]; q[c] += hi[c] * hi[c]; }
        }
    }
#pragma unroll
    for (int o = 16; o > 0; o >>= 1) {
#pragma unroll
        for (int c = 0; c < 4; c++) {
            s[c] += __shfl_down_sync(0xffffffffu, s[c], o);
            q[c] += __shfl_down_sync(0xffffffffu, q[c], o);
        }
    }
    if (lane == 0) {
#pragma unroll
        for (int c = 0; c < 4; c++) {
            atomicAdd(&g_sum[j0 + c], (double)s[c]);
            atomicAdd(&g_sumsq[j0 + c], (double)q[c]);
        }
    }
}

// ---------------- shortcut GEMM: out = X @ Wsc + bsc ----------------
__global__ __launch_bounds__(256) void k_sc(const float* __restrict__ X, const float* __restrict__ W,
                     const float* __restrict__ bias, float* __restrict__ out) {
    __shared__ float Ws[4096];
    __shared__ float Xs[64 * 68];
    int tid = threadIdx.x;
    for (int i = tid; i < 4096; i += 256) Ws[i] = W[i];
    int base = blockIdx.x * 64;
    for (int i = tid; i < 1024; i += 256) {
        int r = i >> 4, c = i & 15;
        int row = base + r;
        float4 v = make_float4(0.f, 0.f, 0.f, 0.f);
        if (row < NN) v = ((const float4*)(X + (size_t)row * 64))[c];
        *(float4*)(Xs + r * 68 + c * 4) = v;
    }
    __syncthreads();
    int rg = tid >> 4, jc = tid & 15;
    int r0 = rg * 4, j0 = jc * 4;
    float acc[4][4];
    float4 bv = *(const float4*)(bias + j0);
#pragma unroll
    for (int i = 0; i < 4; i++) {
        acc[i][0] = bv.x; acc[i][1] = bv.y; acc[i][2] = bv.z; acc[i][3] = bv.w;
    }
    for (int d4 = 0; d4 < 16; d4++) {
        float xa[4][4];
#pragma unroll
        for (int i = 0; i < 4; i++) {
            float4 v = *(const float4*)(Xs + (r0 + i) * 68 + d4 * 4);
            xa[i][0] = v.x; xa[i][1] = v.y; xa[i][2] = v.z; xa[i][3] = v.w;
        }
#pragma unroll
        for (int dd = 0; dd < 4; dd++) {
            float4 w = *(const float4*)(Ws + (d4 * 4 + dd) * 64 + j0);
#pragma unroll
            for (int i = 0; i < 4; i++) {
                float xx = xa[i][dd];
                acc[i][0] += xx * w.x; acc[i][1] += xx * w.y;
                acc[i][2] += xx * w.z; acc[i][3] += xx * w.w;
            }
        }
    }
#pragma unroll
    for (int i = 0; i < 4; i++) {
        int row = base + r0 + i;
        if (row < NN)
            *(float4*)(out + (size_t)row * 64 + j0) =
                make_float4(acc[i][0], acc[i][1], acc[i][2], acc[i][3]);
    }
}

__global__ void k_finalize(const float* __restrict__ g, const float* __restrict__ be) {
    int j = threadIdx.x;
    double mu = g_sum[j] / (double)NN;
    double var = g_sumsq[j] / (double)NN - mu * mu;
    float sc = g[j] * (float)(1.0 / sqrt(var + 1e-5));
    g_scale[j] = sc;
    g_shift[j] = be[j] - (float)mu * sc;
}

// ---------------- BN apply + leaky ReLU (in place) ----------------
__global__ void k_apply(float* __restrict__ H) {
    int i = blockIdx.x * blockDim.x + threadIdx.x;
    if (i < NN * 64) {
        int j = i & 63;
        float v = H[i] * g_scale[j] + g_shift[j];
        H[i] = v > 0.f ? v : 0.01f * v;
    }
}

// ---------------- layer 3: BN apply + lrelu + shortcut + segment-max pool ----------------
__global__ void k_apply3(const float* __restrict__ pre, const float* __restrict__ sc,
                         const int* __restrict__ batch) {
    int i = blockIdx.x * blockDim.x + threadIdx.x;
    if (i >= NN * 64) return;
    int j = i & 63, row = i >> 6;
    float v = pre[i] * g_scale[j] + g_shift[j];
    v = v > 0.f ? v : 0.01f * v;
    v += sc[i];
    atomicMax(&g_pooled[batch[row] * 64 + j], enc_f32(v));
}

// ---------------- final: pooled @ w_lin + b_lin ----------------
__global__ void k_final(const float* __restrict__ wlin, const float* __restrict__ blin,
                        float* __restrict__ out) {
    int g = blockIdx.x, j = threadIdx.x;
    float v = dec_f32(g_pooled[g * 64 + j]) * wlin[j];
#pragma unroll
    for (int o = 16; o > 0; o >>= 1) v += __shfl_down_sync(0xffffffffu, v, o);
    __shared__ float s2[2];
    if ((j & 31) == 0) s2[j >> 5] = v;
    __syncthreads();
    if (j == 0) out[g] = s2[0] + s2[1] + blin[0];
}

// ---------------- launcher ----------------
extern "C" void kernel_launch(void* const* d_in, const int* in_sizes, int n_in,
                              void* d_out, int out_size) {
    const float* x     = (const float*)d_in[0];
    const int*   ei    = (const int*)d_in[1];
    const int*   batch = (const int*)d_in[2];
    const float* W[3]  = {(const float*)d_in[3], (const float*)d_in[5], (const float*)d_in[7]};
    const float* B[3]  = {(const float*)d_in[4], (const float*)d_in[6], (const float*)d_in[8]};
    const float* Ga[3] = {(const float*)d_in[9], (const float*)d_in[11], (const float*)d_in[13]};
    const float* Be[3] = {(const float*)d_in[10], (const float*)d_in[12], (const float*)d_in[14]};
    const float* wsc  = (const float*)d_in[15];
    const float* bsc  = (const float*)d_in[16];
    const float* wlin = (const float*)d_in[17];
    const float* blin = (const float*)d_in[18];
    float* out = (float*)d_out;

    const int GEMM_SMEM = 2 * 192 * 128 * 4;   // 196608 B
    cudaFuncSetAttribute(k_gemm3, cudaFuncAttributeMaxDynamicSharedMemorySize, GEMM_SMEM);

    void *pA, *pB, *pC, *pcnt, *psum, *psumsq, *ppool;
    cudaGetSymbolAddress(&pA, g_bufA);
    cudaGetSymbolAddress(&pB, g_bufB);
    cudaGetSymbolAddress(&pC, g_bufC);
    cudaGetSymbolAddress(&pcnt, g_cnt);
    cudaGetSymbolAddress(&psum, g_sum);
    cudaGetSymbolAddress(&psumsq, g_sumsq);
    cudaGetSymbolAddress(&ppool, g_pooled);

    float* bufA = (float*)pA;
    float* bufB = (float*)pB;
    float* bufC = (float*)pC;

    const int EB = (EE + 255) / 256;
    const int NB = (NN + 255) / 256;
    const int FB = (NN * 64 + 255) / 256;
    const int GB = (NN + 63) / 64;             // k_sc grid
    const int RB = (NN + 127) / 128;           // k_gemm3 grid
    const int SPB = (NN + 7) / 8;              // spmm grid

    // ---- CSR build ----
    cudaMemsetAsync(pcnt, 0, NN * sizeof(int));
    k_deg<<<EB, 256>>>(ei);
    k_scan1<<<SCAN_B, 256>>>();
    k_scan2<<<1, 512>>>();
    k_scan3<<<NB, 256>>>();
    k_fill<<<EB, 256>>>(ei);

    // ---- layers ----
    const float* Zcur = x;
    for (int l = 0; l < 3; l++) {
        k_spmm_csr<<<SPB, 256>>>((const float2*)Zcur, (float2*)bufA);   // T1
        k_spmm_csr<<<SPB, 256>>>((const float2*)bufA, (float2*)bufB);   // P
        cudaMemsetAsync(psum, 0, 64 * sizeof(double));
        cudaMemsetAsync(psumsq, 0, 64 * sizeof(double));
        k_gemm3<<<RB, 512, GEMM_SMEM>>>(Zcur, bufA, bufB, W[l], B[l], bufC);
        k_finalize<<<1, 64>>>(Ga[l], Be[l]);
        if (l < 2) k_apply<<<FB, 256>>>(bufC);
        Zcur = bufC;
    }

    k_sc<<<GB, 256>>>(x, wsc, bsc, bufA);
    cudaMemsetAsync(ppool, 0, GG * 64 * sizeof(unsigned));
    k_apply3<<<FB, 256>>>(bufC, bufA, batch);
    k_final<<<GG, 64>>>(wlin, blin, out);
}